// round 1
// baseline (speedup 1.0000x reference)
#include <cuda_runtime.h>

// Problem constants: B=8, H=W=128, C=256, NUM_HEADS=8, HD=32, WINDOW=8
// tokens = 8*128*128 = 131072
#define TOKENS 131072

// Scratch (allocation-free rule: device globals)
__device__ float g_qkv[100663296u];  // [token][3][head][32]  = 131072*768
__device__ float g_att[33554432u];   // [token][head*32+d]    = 131072*256

// ---------------------------------------------------------------------------
// Tiled FP32 GEMM: C[M,N] = A[M,256] @ B[256,N] (+ bias). BM=BN=128, BK=8.
// 256 threads, 8x8 register micro-tile per thread.
// ---------------------------------------------------------------------------
__global__ __launch_bounds__(256) void gemm_tiled(
    const float* __restrict__ A, const float* __restrict__ B,
    const float* __restrict__ bias, float* __restrict__ C, int N)
{
    __shared__ float As[8][128];   // transposed A tile: As[k][row]
    __shared__ float Bs[8][128];   // Bs[k][col]

    const int tid = threadIdx.x;
    const int bm  = blockIdx.x * 128;
    const int bn  = blockIdx.y * 128;
    const int ty  = tid >> 4;          // 0..15
    const int tx  = tid & 15;          // 0..15
    const int arow = tid >> 1;         // 0..127
    const int acol = (tid & 1) * 4;    // 0 or 4
    const int brow = tid >> 5;         // 0..7
    const int bcol = (tid & 31) * 4;   // 0..124

    float acc[8][8];
#pragma unroll
    for (int i = 0; i < 8; i++)
#pragma unroll
        for (int j = 0; j < 8; j++) acc[i][j] = 0.f;

    const float* aptr = A + (size_t)(bm + arow) * 256 + acol;
    const float* bptr = B + (size_t)brow * N + bn + bcol;

    for (int k0 = 0; k0 < 256; k0 += 8) {
        float4 av = *(const float4*)(aptr + k0);
        float4 bv = *(const float4*)(bptr + (size_t)k0 * N);
        As[acol + 0][arow] = av.x;
        As[acol + 1][arow] = av.y;
        As[acol + 2][arow] = av.z;
        As[acol + 3][arow] = av.w;
        *(float4*)&Bs[brow][bcol] = bv;
        __syncthreads();
#pragma unroll
        for (int k = 0; k < 8; k++) {
            float4 a0 = *(const float4*)&As[k][ty * 8];
            float4 a1 = *(const float4*)&As[k][ty * 8 + 4];
            float4 b0 = *(const float4*)&Bs[k][tx * 8];
            float4 b1 = *(const float4*)&Bs[k][tx * 8 + 4];
            float a[8] = {a0.x, a0.y, a0.z, a0.w, a1.x, a1.y, a1.z, a1.w};
            float b[8] = {b0.x, b0.y, b0.z, b0.w, b1.x, b1.y, b1.z, b1.w};
#pragma unroll
            for (int i = 0; i < 8; i++)
#pragma unroll
                for (int j = 0; j < 8; j++) acc[i][j] += a[i] * b[j];
        }
        __syncthreads();
    }

#pragma unroll
    for (int i = 0; i < 8; i++) {
        size_t row = (size_t)(bm + ty * 8 + i);
#pragma unroll
        for (int j = 0; j < 8; j += 4) {
            int col = bn + tx * 8 + j;
            float4 v = make_float4(acc[i][j], acc[i][j + 1], acc[i][j + 2], acc[i][j + 3]);
            if (bias) {
                v.x += bias[col];     v.y += bias[col + 1];
                v.z += bias[col + 2]; v.w += bias[col + 3];
            }
            *(float4*)&C[row * N + col] = v;
        }
    }
}

// ---------------------------------------------------------------------------
// Local window attention: heads 0..3, 8x8 windows (64 tokens each).
// grid = (2048 windows, 2 head-pairs), 128 threads: (head-in-pair, query row).
// One thread = one query row; K,V for both heads staged in smem (32KB).
// ---------------------------------------------------------------------------
__global__ __launch_bounds__(128) void attn_local(const float* __restrict__ qkv,
                                                  float* __restrict__ att)
{
    __shared__ float Ks[2][64][32];
    __shared__ float Vs[2][64][32];

    const int wid = blockIdx.x;          // b*256 + wy*16 + wx
    const int b  = wid >> 8;
    const int wy = (wid >> 4) & 15;
    const int wx = wid & 15;
    const int tid = threadIdx.x;
    const int hh = tid >> 6;                     // 0..1 head within pair
    const int h  = (int)blockIdx.y * 2 + hh;     // global head 0..3
    const int r  = tid & 63;                     // query/key row in window

    const int i = r >> 3, j = r & 7;
    const size_t token = ((size_t)(b * 128 + wy * 8 + i)) * 128 + (wx * 8 + j);
    const float* kp = qkv + token * 768 + 256 + h * 32;
    const float* vp = qkv + token * 768 + 512 + h * 32;
#pragma unroll
    for (int d = 0; d < 32; d += 4) {
        *(float4*)&Ks[hh][r][d] = *(const float4*)&kp[d];
        *(float4*)&Vs[hh][r][d] = *(const float4*)&vp[d];
    }

    float q[32];
    const float* qp = qkv + token * 768 + h * 32;
#pragma unroll
    for (int d = 0; d < 32; d += 4) {
        float4 t = *(const float4*)&qp[d];
        q[d] = t.x; q[d + 1] = t.y; q[d + 2] = t.z; q[d + 3] = t.w;
    }
    __syncthreads();

    const float scale = 0.17677669529663687f;  // 1/sqrt(32)
    float m = -3.0e38f, l = 0.f;
    float acc[32];
#pragma unroll
    for (int d = 0; d < 32; d++) acc[d] = 0.f;

    for (int t = 0; t < 64; t++) {
        float s = 0.f;
#pragma unroll
        for (int d = 0; d < 32; d += 4) {
            float4 kv = *(const float4*)&Ks[hh][t][d];
            s += q[d] * kv.x + q[d + 1] * kv.y + q[d + 2] * kv.z + q[d + 3] * kv.w;
        }
        s *= scale;
        if (s > m) {
            float corr = __expf(m - s);
            l *= corr;
#pragma unroll
            for (int d = 0; d < 32; d++) acc[d] *= corr;
            m = s;
        }
        float p = __expf(s - m);
        l += p;
#pragma unroll
        for (int d = 0; d < 32; d += 4) {
            float4 vv = *(const float4*)&Vs[hh][t][d];
            acc[d]     += p * vv.x;
            acc[d + 1] += p * vv.y;
            acc[d + 2] += p * vv.z;
            acc[d + 3] += p * vv.w;
        }
    }

    const float inv = 1.f / l;
    float* op = att + token * 256 + h * 32;
#pragma unroll
    for (int d = 0; d < 32; d += 4) {
        float4 o = make_float4(acc[d] * inv, acc[d + 1] * inv,
                               acc[d + 2] * inv, acc[d + 3] * inv);
        *(float4*)&op[d] = o;
    }
}

// ---------------------------------------------------------------------------
// Grid (dilated) attention: heads 4..7, each cell (b,s1,s2) attends over the
// 16x16 grid of windows (256 tokens). grid = (512 cells, 4 heads), 256 threads.
// One thread = one query row; keys streamed in 64-row smem tiles, online softmax.
// ---------------------------------------------------------------------------
__global__ __launch_bounds__(256) void attn_global(const float* __restrict__ qkv,
                                                   float* __restrict__ att)
{
    __shared__ float Ks[64][32];
    __shared__ float Vs[64][32];

    const int cid = blockIdx.x;          // b*64 + s1*8 + s2
    const int b  = cid >> 6;
    const int s1 = (cid >> 3) & 7;
    const int s2 = cid & 7;
    const int h  = 4 + (int)blockIdx.y;  // global head 4..7
    const int t  = threadIdx.x;          // query row 0..255

    const int wy = t >> 4, wx = t & 15;
    const size_t token = ((size_t)(b * 128 + wy * 8 + s1)) * 128 + (wx * 8 + s2);

    float q[32];
    const float* qp = qkv + token * 768 + h * 32;
#pragma unroll
    for (int d = 0; d < 32; d += 4) {
        float4 tq = *(const float4*)&qp[d];
        q[d] = tq.x; q[d + 1] = tq.y; q[d + 2] = tq.z; q[d + 3] = tq.w;
    }

    const float scale = 0.17677669529663687f;
    float m = -3.0e38f, l = 0.f;
    float acc[32];
#pragma unroll
    for (int d = 0; d < 32; d++) acc[d] = 0.f;

    const int rr  = t >> 2;        // 0..63 key row this thread loads
    const int seg = (t & 3) * 8;   // 0,8,16,24

    for (int kt = 0; kt < 256; kt += 64) {
        const int kk = kt + rr;
        const size_t ktok =
            ((size_t)(b * 128 + (kk >> 4) * 8 + s1)) * 128 + ((kk & 15) * 8 + s2);
        const float* kp = qkv + ktok * 768 + 256 + h * 32 + seg;
        const float* vp = qkv + ktok * 768 + 512 + h * 32 + seg;
        *(float4*)&Ks[rr][seg]     = *(const float4*)kp;
        *(float4*)&Ks[rr][seg + 4] = *(const float4*)(kp + 4);
        *(float4*)&Vs[rr][seg]     = *(const float4*)vp;
        *(float4*)&Vs[rr][seg + 4] = *(const float4*)(vp + 4);
        __syncthreads();

        for (int tt = 0; tt < 64; tt++) {
            float s = 0.f;
#pragma unroll
            for (int d = 0; d < 32; d += 4) {
                float4 kv = *(const float4*)&Ks[tt][d];
                s += q[d] * kv.x + q[d + 1] * kv.y + q[d + 2] * kv.z + q[d + 3] * kv.w;
            }
            s *= scale;
            if (s > m) {
                float corr = __expf(m - s);
                l *= corr;
#pragma unroll
                for (int d = 0; d < 32; d++) acc[d] *= corr;
                m = s;
            }
            float p = __expf(s - m);
            l += p;
#pragma unroll
            for (int d = 0; d < 32; d += 4) {
                float4 vv = *(const float4*)&Vs[tt][d];
                acc[d]     += p * vv.x;
                acc[d + 1] += p * vv.y;
                acc[d + 2] += p * vv.z;
                acc[d + 3] += p * vv.w;
            }
        }
        __syncthreads();
    }

    const float inv = 1.f / l;
    float* op = att + token * 256 + h * 32;
#pragma unroll
    for (int d = 0; d < 32; d += 4) {
        float4 o = make_float4(acc[d] * inv, acc[d + 1] * inv,
                               acc[d + 2] * inv, acc[d + 3] * inv);
        *(float4*)&op[d] = o;
    }
}

// ---------------------------------------------------------------------------
// Launch: QKV GEMM -> local attn -> grid attn -> output projection (+bias)
// ---------------------------------------------------------------------------
extern "C" void kernel_launch(void* const* d_in, const int* in_sizes, int n_in,
                              void* d_out, int out_size)
{
    (void)in_sizes; (void)n_in; (void)out_size;
    const float* x     = (const float*)d_in[0];
    const float* Wqkv  = (const float*)d_in[1];
    const float* Wproj = (const float*)d_in[2];
    const float* bproj = (const float*)d_in[3];
    float* out = (float*)d_out;

    float* qkv = nullptr;
    float* att = nullptr;
    cudaGetSymbolAddress((void**)&qkv, g_qkv);
    cudaGetSymbolAddress((void**)&att, g_att);

    // 1) QKV = x @ W_qkv : [131072,256]x[256,768]
    gemm_tiled<<<dim3(1024, 6), 256>>>(x, Wqkv, nullptr, qkv, 768);
    // 2) local window attention (heads 0..3)
    attn_local<<<dim3(2048, 2), 128>>>(qkv, att);
    // 3) dilated grid attention (heads 4..7)
    attn_global<<<dim3(512, 4), 256>>>(qkv, att);
    // 4) out = att @ W_proj + b_proj : [131072,256]x[256,256]
    gemm_tiled<<<dim3(1024, 2), 256>>>(att, Wproj, bproj, out, 256);
}

// round 2
// speedup vs baseline: 1.1522x; 1.1522x over previous
#include <cuda_runtime.h>
#include <mma.h>
using namespace nvcuda;

// Problem constants: B=8, H=W=128, C=256, NUM_HEADS=8, HD=32, WINDOW=8
#define TOKENS 131072

// Scratch (allocation-free rule: device globals)
__device__ float g_qkv[100663296u];  // [token][3][head][32]  = 131072*768
__device__ float g_att[33554432u];   // [token][head*32+d]    = 131072*256

// ---------------------------------------------------------------------------
// TF32 tensor-core GEMM: C[M,N] = A[M,256] @ B[256,N] (+ bias).
// BM=BN=128, BK=32. 256 threads = 8 warps in 2x4; warp tile 64x32 (4x2 wmma).
// ---------------------------------------------------------------------------
__global__ __launch_bounds__(256) void gemm_wmma(
    const float* __restrict__ A, const float* __restrict__ B,
    const float* __restrict__ bias, float* __restrict__ C, int N)
{
    __shared__ float As[128][36];   // ldm 36 (mult of 4)
    __shared__ float Bs[32][132];   // ldm 132

    const int tid  = threadIdx.x;
    const int warp = tid >> 5;
    const int lane = tid & 31;
    const int wm = warp >> 2;       // 0..1  (64 rows each)
    const int wn = warp & 3;        // 0..3  (32 cols each)
    const int bm = blockIdx.x * 128;
    const int bn = blockIdx.y * 128;

    wmma::fragment<wmma::accumulator, 16, 16, 8, float> acc[4][2];
#pragma unroll
    for (int i = 0; i < 4; i++)
#pragma unroll
        for (int j = 0; j < 2; j++) wmma::fill_fragment(acc[i][j], 0.f);

    for (int k0 = 0; k0 < 256; k0 += 32) {
#pragma unroll
        for (int t = 0; t < 4; t++) {
            int idx = tid + t * 256;                  // 0..1023
            int ar = idx >> 3, ac = (idx & 7) * 4;    // A: 128 x 32
            float4 av = *(const float4*)(A + (size_t)(bm + ar) * 256 + k0 + ac);
            As[ar][ac + 0] = wmma::__float_to_tf32(av.x);
            As[ar][ac + 1] = wmma::__float_to_tf32(av.y);
            As[ar][ac + 2] = wmma::__float_to_tf32(av.z);
            As[ar][ac + 3] = wmma::__float_to_tf32(av.w);
            int br = idx >> 5, bc = (idx & 31) * 4;   // B: 32 x 128
            float4 bv = *(const float4*)(B + (size_t)(k0 + br) * N + bn + bc);
            Bs[br][bc + 0] = wmma::__float_to_tf32(bv.x);
            Bs[br][bc + 1] = wmma::__float_to_tf32(bv.y);
            Bs[br][bc + 2] = wmma::__float_to_tf32(bv.z);
            Bs[br][bc + 3] = wmma::__float_to_tf32(bv.w);
        }
        __syncthreads();
#pragma unroll
        for (int kk = 0; kk < 32; kk += 8) {
            wmma::fragment<wmma::matrix_a, 16, 16, 8, wmma::precision::tf32,
                           wmma::row_major> af[4];
            wmma::fragment<wmma::matrix_b, 16, 16, 8, wmma::precision::tf32,
                           wmma::row_major> bf[2];
#pragma unroll
            for (int i = 0; i < 4; i++)
                wmma::load_matrix_sync(af[i], &As[wm * 64 + i * 16][kk], 36);
#pragma unroll
            for (int j = 0; j < 2; j++)
                wmma::load_matrix_sync(bf[j], &Bs[kk][wn * 32 + j * 16], 132);
#pragma unroll
            for (int i = 0; i < 4; i++)
#pragma unroll
                for (int j = 0; j < 2; j++)
                    wmma::mma_sync(acc[i][j], af[i], bf[j], acc[i][j]);
        }
        __syncthreads();
    }

    // Epilogue: bounce each 16x16 tile through a private smem strip, add bias.
    float* wb = &As[0][0] + warp * 320;   // 16 rows x ldm 20
    const int r  = lane >> 1;
    const int c0 = (lane & 1) * 8;
#pragma unroll
    for (int i = 0; i < 4; i++) {
#pragma unroll
        for (int j = 0; j < 2; j++) {
            wmma::store_matrix_sync(wb, acc[i][j], 20, wmma::mem_row_major);
            __syncwarp();
            float4 v0 = *(float4*)&wb[r * 20 + c0];
            float4 v1 = *(float4*)&wb[r * 20 + c0 + 4];
            int grow = bm + wm * 64 + i * 16 + r;
            int gcol = bn + wn * 32 + j * 16 + c0;
            if (bias) {
                v0.x += bias[gcol + 0]; v0.y += bias[gcol + 1];
                v0.z += bias[gcol + 2]; v0.w += bias[gcol + 3];
                v1.x += bias[gcol + 4]; v1.y += bias[gcol + 5];
                v1.z += bias[gcol + 6]; v1.w += bias[gcol + 7];
            }
            *(float4*)&C[(size_t)grow * N + gcol]     = v0;
            *(float4*)&C[(size_t)grow * N + gcol + 4] = v1;
            __syncwarp();
        }
    }
}

// ---------------------------------------------------------------------------
// Local window attention: heads 0..3, 8x8 windows (64 tokens each).
// ---------------------------------------------------------------------------
__global__ __launch_bounds__(128) void attn_local(const float* __restrict__ qkv,
                                                  float* __restrict__ att)
{
    __shared__ float Ks[2][64][32];
    __shared__ float Vs[2][64][32];

    const int wid = blockIdx.x;          // b*256 + wy*16 + wx
    const int b  = wid >> 8;
    const int wy = (wid >> 4) & 15;
    const int wx = wid & 15;
    const int tid = threadIdx.x;
    const int hh = tid >> 6;                     // 0..1 head within pair
    const int h  = (int)blockIdx.y * 2 + hh;     // global head 0..3
    const int r  = tid & 63;                     // query/key row in window

    const int i = r >> 3, j = r & 7;
    const size_t token = ((size_t)(b * 128 + wy * 8 + i)) * 128 + (wx * 8 + j);
    const float* kp = qkv + token * 768 + 256 + h * 32;
    const float* vp = qkv + token * 768 + 512 + h * 32;
#pragma unroll
    for (int d = 0; d < 32; d += 4) {
        *(float4*)&Ks[hh][r][d] = *(const float4*)&kp[d];
        *(float4*)&Vs[hh][r][d] = *(const float4*)&vp[d];
    }

    float q[32];
    const float* qp = qkv + token * 768 + h * 32;
#pragma unroll
    for (int d = 0; d < 32; d += 4) {
        float4 t = *(const float4*)&qp[d];
        q[d] = t.x; q[d + 1] = t.y; q[d + 2] = t.z; q[d + 3] = t.w;
    }
    __syncthreads();

    const float scale = 0.17677669529663687f;  // 1/sqrt(32)
    float m = -3.0e38f, l = 0.f;
    float acc[32];
#pragma unroll
    for (int d = 0; d < 32; d++) acc[d] = 0.f;

    for (int t = 0; t < 64; t++) {
        float s = 0.f;
#pragma unroll
        for (int d = 0; d < 32; d += 4) {
            float4 kv = *(const float4*)&Ks[hh][t][d];
            s += q[d] * kv.x + q[d + 1] * kv.y + q[d + 2] * kv.z + q[d + 3] * kv.w;
        }
        s *= scale;
        if (s > m) {
            float corr = __expf(m - s);
            l *= corr;
#pragma unroll
            for (int d = 0; d < 32; d++) acc[d] *= corr;
            m = s;
        }
        float p = __expf(s - m);
        l += p;
#pragma unroll
        for (int d = 0; d < 32; d += 4) {
            float4 vv = *(const float4*)&Vs[hh][t][d];
            acc[d]     += p * vv.x;
            acc[d + 1] += p * vv.y;
            acc[d + 2] += p * vv.z;
            acc[d + 3] += p * vv.w;
        }
    }

    const float inv = 1.f / l;
    float* op = att + token * 256 + h * 32;
#pragma unroll
    for (int d = 0; d < 32; d += 4) {
        float4 o = make_float4(acc[d] * inv, acc[d + 1] * inv,
                               acc[d + 2] * inv, acc[d + 3] * inv);
        *(float4*)&op[d] = o;
    }
}

// ---------------------------------------------------------------------------
// Grid (dilated) attention: heads 4..7.
// ---------------------------------------------------------------------------
__global__ __launch_bounds__(256) void attn_global(const float* __restrict__ qkv,
                                                   float* __restrict__ att)
{
    __shared__ float Ks[64][32];
    __shared__ float Vs[64][32];

    const int cid = blockIdx.x;          // b*64 + s1*8 + s2
    const int b  = cid >> 6;
    const int s1 = (cid >> 3) & 7;
    const int s2 = cid & 7;
    const int h  = 4 + (int)blockIdx.y;  // global head 4..7
    const int t  = threadIdx.x;          // query row 0..255

    const int wy = t >> 4, wx = t & 15;
    const size_t token = ((size_t)(b * 128 + wy * 8 + s1)) * 128 + (wx * 8 + s2);

    float q[32];
    const float* qp = qkv + token * 768 + h * 32;
#pragma unroll
    for (int d = 0; d < 32; d += 4) {
        float4 tq = *(const float4*)&qp[d];
        q[d] = tq.x; q[d + 1] = tq.y; q[d + 2] = tq.z; q[d + 3] = tq.w;
    }

    const float scale = 0.17677669529663687f;
    float m = -3.0e38f, l = 0.f;
    float acc[32];
#pragma unroll
    for (int d = 0; d < 32; d++) acc[d] = 0.f;

    const int rr  = t >> 2;        // 0..63 key row this thread loads
    const int seg = (t & 3) * 8;   // 0,8,16,24

    for (int kt = 0; kt < 256; kt += 64) {
        const int kk = kt + rr;
        const size_t ktok =
            ((size_t)(b * 128 + (kk >> 4) * 8 + s1)) * 128 + ((kk & 15) * 8 + s2);
        const float* kp = qkv + ktok * 768 + 256 + h * 32 + seg;
        const float* vp = qkv + ktok * 768 + 512 + h * 32 + seg;
        *(float4*)&Ks[rr][seg]     = *(const float4*)kp;
        *(float4*)&Ks[rr][seg + 4] = *(const float4*)(kp + 4);
        *(float4*)&Vs[rr][seg]     = *(const float4*)vp;
        *(float4*)&Vs[rr][seg + 4] = *(const float4*)(vp + 4);
        __syncthreads();

        for (int tt = 0; tt < 64; tt++) {
            float s = 0.f;
#pragma unroll
            for (int d = 0; d < 32; d += 4) {
                float4 kv = *(const float4*)&Ks[tt][d];
                s += q[d] * kv.x + q[d + 1] * kv.y + q[d + 2] * kv.z + q[d + 3] * kv.w;
            }
            s *= scale;
            if (s > m) {
                float corr = __expf(m - s);
                l *= corr;
#pragma unroll
                for (int d = 0; d < 32; d++) acc[d] *= corr;
                m = s;
            }
            float p = __expf(s - m);
            l += p;
#pragma unroll
            for (int d = 0; d < 32; d += 4) {
                float4 vv = *(const float4*)&Vs[tt][d];
                acc[d]     += p * vv.x;
                acc[d + 1] += p * vv.y;
                acc[d + 2] += p * vv.z;
                acc[d + 3] += p * vv.w;
            }
        }
        __syncthreads();
    }

    const float inv = 1.f / l;
    float* op = att + token * 256 + h * 32;
#pragma unroll
    for (int d = 0; d < 32; d += 4) {
        float4 o = make_float4(acc[d] * inv, acc[d + 1] * inv,
                               acc[d + 2] * inv, acc[d + 3] * inv);
        *(float4*)&op[d] = o;
    }
}

// ---------------------------------------------------------------------------
// Launch: QKV GEMM -> local attn -> grid attn -> output projection (+bias)
// ---------------------------------------------------------------------------
extern "C" void kernel_launch(void* const* d_in, const int* in_sizes, int n_in,
                              void* d_out, int out_size)
{
    (void)in_sizes; (void)n_in; (void)out_size;
    const float* x     = (const float*)d_in[0];
    const float* Wqkv  = (const float*)d_in[1];
    const float* Wproj = (const float*)d_in[2];
    const float* bproj = (const float*)d_in[3];
    float* out = (float*)d_out;

    float* qkv = nullptr;
    float* att = nullptr;
    cudaGetSymbolAddress((void**)&qkv, g_qkv);
    cudaGetSymbolAddress((void**)&att, g_att);

    // 1) QKV = x @ W_qkv : [131072,256]x[256,768]
    gemm_wmma<<<dim3(1024, 6), 256>>>(x, Wqkv, nullptr, qkv, 768);
    // 2) local window attention (heads 0..3)
    attn_local<<<dim3(2048, 2), 128>>>(qkv, att);
    // 3) dilated grid attention (heads 4..7)
    attn_global<<<dim3(512, 4), 256>>>(qkv, att);
    // 4) out = att @ W_proj + b_proj : [131072,256]x[256,256]
    gemm_wmma<<<dim3(1024, 2), 256>>>(att, Wproj, bproj, out, 256);
}

// round 3
// speedup vs baseline: 1.4300x; 1.2411x over previous
#include <cuda_runtime.h>
#include <mma.h>
using namespace nvcuda;

// Problem constants: B=8, H=W=128, C=256, NUM_HEADS=8, HD=32, WINDOW=8
#define TOKENS 131072

// Scratch (allocation-free rule: device globals)
__device__ float g_qkv[100663296u];  // [token][3][head][32]  = 131072*768
__device__ float g_att[33554432u];   // [token][head*32+d]    = 131072*256

// ---------------------------------------------------------------------------
// cp.async helpers
// ---------------------------------------------------------------------------
__device__ __forceinline__ void cp_async16(void* smem, const void* gmem) {
    unsigned s = (unsigned)__cvta_generic_to_shared(smem);
    asm volatile("cp.async.cg.shared.global [%0], [%1], 16;\n" :: "r"(s), "l"(gmem));
}
__device__ __forceinline__ void cp_commit() {
    asm volatile("cp.async.commit_group;\n");
}
__device__ __forceinline__ void cp_wait1() {
    asm volatile("cp.async.wait_group 1;\n");
}
__device__ __forceinline__ void cp_wait0() {
    asm volatile("cp.async.wait_group 0;\n");
}

// ---------------------------------------------------------------------------
// TF32 tensor-core GEMM: C[M,N] = A[M,256] @ B[256,N] (+ bias).
// BM=BN=128, BK=16, 2-stage cp.async pipeline. 256 threads = 8 warps (2x4);
// warp tile 64x32 (4x2 wmma m16n16k8). grid.x = N/128 (fast) for A L2 reuse.
// ---------------------------------------------------------------------------
__global__ __launch_bounds__(256, 2) void gemm_wmma(
    const float* __restrict__ A, const float* __restrict__ B,
    const float* __restrict__ bias, float* __restrict__ C, int N)
{
    __shared__ float As[2][128][20];   // 16 payload + pad, row = 80B (16B mult)
    __shared__ float Bs[2][16][132];   // row = 528B (16B mult)

    const int tid  = threadIdx.x;
    const int warp = tid >> 5;
    const int lane = tid & 31;
    const int wm = warp >> 2;          // 0..1
    const int wn = warp & 3;           // 0..3
    const int bn = blockIdx.x * 128;   // fast dim = columns -> A tile L2 reuse
    const int bm = blockIdx.y * 128;

    wmma::fragment<wmma::accumulator, 16, 16, 8, float> acc[4][2];
#pragma unroll
    for (int i = 0; i < 4; i++)
#pragma unroll
        for (int j = 0; j < 2; j++) wmma::fill_fragment(acc[i][j], 0.f);

    const int a_r  = tid >> 1;            // idx mapping: 2 float4/thread for A
    const int a_c0 = (tid & 1) * 2;       // float4 slot 0..3 (two per thread)
    const int b_r  = tid >> 4;            // 2 float4/thread for B
    const int b_c0 = (tid & 15) * 2;

    auto load_tile = [&](int s, int k0) {
#pragma unroll
        for (int t = 0; t < 2; t++) {
            // A: 128 rows x 16 floats (4 float4/row), 512 float4 total
            int ar = a_r, ac = (a_c0 + t) * 4;
            cp_async16(&As[s][ar][ac], A + (size_t)(bm + ar) * 256 + k0 + ac);
            // B: 16 rows x 128 floats (32 float4/row), 512 float4 total
            int br = b_r, bc = (b_c0 + t) * 4;
            cp_async16(&Bs[s][br][bc], B + (size_t)(k0 + br) * N + bn + bc);
        }
        cp_commit();
    };

    load_tile(0, 0);

    const int NK = 16;  // 256 / 16
    for (int kt = 0; kt < NK; kt++) {
        const int cur = kt & 1;
        if (kt + 1 < NK) { load_tile(cur ^ 1, (kt + 1) * 16); cp_wait1(); }
        else             { cp_wait0(); }
        __syncthreads();

#pragma unroll
        for (int kk = 0; kk < 16; kk += 8) {
            wmma::fragment<wmma::matrix_a, 16, 16, 8, wmma::precision::tf32,
                           wmma::row_major> af[4];
            wmma::fragment<wmma::matrix_b, 16, 16, 8, wmma::precision::tf32,
                           wmma::row_major> bf[2];
#pragma unroll
            for (int i = 0; i < 4; i++) {
                wmma::load_matrix_sync(af[i], &As[cur][wm * 64 + i * 16][kk], 20);
#pragma unroll
                for (int e = 0; e < af[i].num_elements; e++)
                    af[i].x[e] = wmma::__float_to_tf32(af[i].x[e]);
            }
#pragma unroll
            for (int j = 0; j < 2; j++) {
                wmma::load_matrix_sync(bf[j], &Bs[cur][kk][wn * 32 + j * 16], 132);
#pragma unroll
                for (int e = 0; e < bf[j].num_elements; e++)
                    bf[j].x[e] = wmma::__float_to_tf32(bf[j].x[e]);
            }
#pragma unroll
            for (int i = 0; i < 4; i++)
#pragma unroll
                for (int j = 0; j < 2; j++)
                    wmma::mma_sync(acc[i][j], af[i], bf[j], acc[i][j]);
        }
        __syncthreads();
    }

    // Epilogue: bounce each 16x16 tile through a private smem strip, add bias.
    float* wb = &As[0][0][0] + warp * 320;   // 16 rows x ldm 20
    const int r  = lane >> 1;
    const int c0 = (lane & 1) * 8;
#pragma unroll
    for (int i = 0; i < 4; i++) {
#pragma unroll
        for (int j = 0; j < 2; j++) {
            wmma::store_matrix_sync(wb, acc[i][j], 20, wmma::mem_row_major);
            __syncwarp();
            float4 v0 = *(float4*)&wb[r * 20 + c0];
            float4 v1 = *(float4*)&wb[r * 20 + c0 + 4];
            int grow = bm + wm * 64 + i * 16 + r;
            int gcol = bn + wn * 32 + j * 16 + c0;
            if (bias) {
                v0.x += bias[gcol + 0]; v0.y += bias[gcol + 1];
                v0.z += bias[gcol + 2]; v0.w += bias[gcol + 3];
                v1.x += bias[gcol + 4]; v1.y += bias[gcol + 5];
                v1.z += bias[gcol + 6]; v1.w += bias[gcol + 7];
            }
            *(float4*)&C[(size_t)grow * N + gcol]     = v0;
            *(float4*)&C[(size_t)grow * N + gcol + 4] = v1;
            __syncwarp();
        }
    }
}

// ---------------------------------------------------------------------------
// Local window attention: heads 0..3, 8x8 windows (64 tokens each).
// Chunked (8-key) online softmax for ILP: 8 independent dots, 1 rescale/chunk.
// ---------------------------------------------------------------------------
__global__ __launch_bounds__(128) void attn_local(const float* __restrict__ qkv,
                                                  float* __restrict__ att)
{
    __shared__ float Ks[2][64][32];
    __shared__ float Vs[2][64][32];

    const int wid = blockIdx.x;          // b*256 + wy*16 + wx
    const int b  = wid >> 8;
    const int wy = (wid >> 4) & 15;
    const int wx = wid & 15;
    const int tid = threadIdx.x;
    const int hh = tid >> 6;                     // 0..1 head within pair
    const int h  = (int)blockIdx.y * 2 + hh;     // global head 0..3
    const int r  = tid & 63;                     // query/key row in window

    const int i = r >> 3, j = r & 7;
    const size_t token = ((size_t)(b * 128 + wy * 8 + i)) * 128 + (wx * 8 + j);
    const float* kp = qkv + token * 768 + 256 + h * 32;
    const float* vp = qkv + token * 768 + 512 + h * 32;
#pragma unroll
    for (int d = 0; d < 32; d += 4) {
        *(float4*)&Ks[hh][r][d] = *(const float4*)&kp[d];
        *(float4*)&Vs[hh][r][d] = *(const float4*)&vp[d];
    }

    float q[32];
    const float* qp = qkv + token * 768 + h * 32;
#pragma unroll
    for (int d = 0; d < 32; d += 4) {
        float4 t = *(const float4*)&qp[d];
        q[d] = t.x; q[d + 1] = t.y; q[d + 2] = t.z; q[d + 3] = t.w;
    }
    __syncthreads();

    const float scale = 0.17677669529663687f;  // 1/sqrt(32)
    float m = -3.0e38f, l = 0.f;
    float acc[32];
#pragma unroll
    for (int d = 0; d < 32; d++) acc[d] = 0.f;

    for (int t0 = 0; t0 < 64; t0 += 8) {
        float sc[8];
#pragma unroll
        for (int u = 0; u < 8; u++) {
            float s = 0.f;
#pragma unroll
            for (int d = 0; d < 32; d += 4) {
                float4 kv = *(const float4*)&Ks[hh][t0 + u][d];
                s += q[d] * kv.x + q[d + 1] * kv.y + q[d + 2] * kv.z + q[d + 3] * kv.w;
            }
            sc[u] = s * scale;
        }
        float cm = sc[0];
#pragma unroll
        for (int u = 1; u < 8; u++) cm = fmaxf(cm, sc[u]);
        if (cm > m) {
            float corr = __expf(m - cm);
            l *= corr;
#pragma unroll
            for (int d = 0; d < 32; d++) acc[d] *= corr;
            m = cm;
        }
#pragma unroll
        for (int u = 0; u < 8; u++) {
            float p = __expf(sc[u] - m);
            l += p;
#pragma unroll
            for (int d = 0; d < 32; d += 4) {
                float4 vv = *(const float4*)&Vs[hh][t0 + u][d];
                acc[d]     += p * vv.x;
                acc[d + 1] += p * vv.y;
                acc[d + 2] += p * vv.z;
                acc[d + 3] += p * vv.w;
            }
        }
    }

    const float inv = 1.f / l;
    float* op = att + token * 256 + h * 32;
#pragma unroll
    for (int d = 0; d < 32; d += 4) {
        float4 o = make_float4(acc[d] * inv, acc[d + 1] * inv,
                               acc[d + 2] * inv, acc[d + 3] * inv);
        *(float4*)&op[d] = o;
    }
}

// ---------------------------------------------------------------------------
// Grid (dilated) attention: heads 4..7, chunked online softmax.
// ---------------------------------------------------------------------------
__global__ __launch_bounds__(256) void attn_global(const float* __restrict__ qkv,
                                                   float* __restrict__ att)
{
    __shared__ float Ks[64][32];
    __shared__ float Vs[64][32];

    const int cid = blockIdx.x;          // b*64 + s1*8 + s2
    const int b  = cid >> 6;
    const int s1 = (cid >> 3) & 7;
    const int s2 = cid & 7;
    const int h  = 4 + (int)blockIdx.y;  // global head 4..7
    const int t  = threadIdx.x;          // query row 0..255

    const int wy = t >> 4, wx = t & 15;
    const size_t token = ((size_t)(b * 128 + wy * 8 + s1)) * 128 + (wx * 8 + s2);

    float q[32];
    const float* qp = qkv + token * 768 + h * 32;
#pragma unroll
    for (int d = 0; d < 32; d += 4) {
        float4 tq = *(const float4*)&qp[d];
        q[d] = tq.x; q[d + 1] = tq.y; q[d + 2] = tq.z; q[d + 3] = tq.w;
    }

    const float scale = 0.17677669529663687f;
    float m = -3.0e38f, l = 0.f;
    float acc[32];
#pragma unroll
    for (int d = 0; d < 32; d++) acc[d] = 0.f;

    const int rr  = t >> 2;        // 0..63 key row this thread loads
    const int seg = (t & 3) * 8;   // 0,8,16,24

    for (int kt = 0; kt < 256; kt += 64) {
        const int kk = kt + rr;
        const size_t ktok =
            ((size_t)(b * 128 + (kk >> 4) * 8 + s1)) * 128 + ((kk & 15) * 8 + s2);
        const float* kp = qkv + ktok * 768 + 256 + h * 32 + seg;
        const float* vp = qkv + ktok * 768 + 512 + h * 32 + seg;
        *(float4*)&Ks[rr][seg]     = *(const float4*)kp;
        *(float4*)&Ks[rr][seg + 4] = *(const float4*)(kp + 4);
        *(float4*)&Vs[rr][seg]     = *(const float4*)vp;
        *(float4*)&Vs[rr][seg + 4] = *(const float4*)(vp + 4);
        __syncthreads();

        for (int t0 = 0; t0 < 64; t0 += 8) {
            float sc[8];
#pragma unroll
            for (int u = 0; u < 8; u++) {
                float s = 0.f;
#pragma unroll
                for (int d = 0; d < 32; d += 4) {
                    float4 kv = *(const float4*)&Ks[t0 + u][d];
                    s += q[d] * kv.x + q[d + 1] * kv.y + q[d + 2] * kv.z + q[d + 3] * kv.w;
                }
                sc[u] = s * scale;
            }
            float cm = sc[0];
#pragma unroll
            for (int u = 1; u < 8; u++) cm = fmaxf(cm, sc[u]);
            if (cm > m) {
                float corr = __expf(m - cm);
                l *= corr;
#pragma unroll
                for (int d = 0; d < 32; d++) acc[d] *= corr;
                m = cm;
            }
#pragma unroll
            for (int u = 0; u < 8; u++) {
                float p = __expf(sc[u] - m);
                l += p;
#pragma unroll
                for (int d = 0; d < 32; d += 4) {
                    float4 vv = *(const float4*)&Vs[t0 + u][d];
                    acc[d]     += p * vv.x;
                    acc[d + 1] += p * vv.y;
                    acc[d + 2] += p * vv.z;
                    acc[d + 3] += p * vv.w;
                }
            }
        }
        __syncthreads();
    }

    const float inv = 1.f / l;
    float* op = att + token * 256 + h * 32;
#pragma unroll
    for (int d = 0; d < 32; d += 4) {
        float4 o = make_float4(acc[d] * inv, acc[d + 1] * inv,
                               acc[d + 2] * inv, acc[d + 3] * inv);
        *(float4*)&op[d] = o;
    }
}

// ---------------------------------------------------------------------------
// Launch: QKV GEMM -> local attn -> grid attn -> output projection (+bias)
// ---------------------------------------------------------------------------
extern "C" void kernel_launch(void* const* d_in, const int* in_sizes, int n_in,
                              void* d_out, int out_size)
{
    (void)in_sizes; (void)n_in; (void)out_size;
    const float* x     = (const float*)d_in[0];
    const float* Wqkv  = (const float*)d_in[1];
    const float* Wproj = (const float*)d_in[2];
    const float* bproj = (const float*)d_in[3];
    float* out = (float*)d_out;

    float* qkv = nullptr;
    float* att = nullptr;
    cudaGetSymbolAddress((void**)&qkv, g_qkv);
    cudaGetSymbolAddress((void**)&att, g_att);

    // 1) QKV = x @ W_qkv : [131072,256]x[256,768]  (grid.x = cols for L2 reuse)
    gemm_wmma<<<dim3(6, 1024), 256>>>(x, Wqkv, nullptr, qkv, 768);
    // 2) local window attention (heads 0..3)
    attn_local<<<dim3(2048, 2), 128>>>(qkv, att);
    // 3) dilated grid attention (heads 4..7)
    attn_global<<<dim3(512, 4), 256>>>(qkv, att);
    // 4) out = att @ W_proj + b_proj : [131072,256]x[256,256]
    gemm_wmma<<<dim3(2, 1024), 256>>>(att, Wproj, bproj, out, 256);
}

// round 4
// speedup vs baseline: 1.5318x; 1.0712x over previous
#include <cuda_runtime.h>
#include <mma.h>
using namespace nvcuda;

// Problem constants: B=8, H=W=128, C=256, NUM_HEADS=8, HD=32, WINDOW=8
#define TOKENS 131072

// Scratch (allocation-free rule: device globals)
__device__ float g_qkv[100663296u];  // [token][3][head][32]
__device__ float g_att[33554432u];   // [token][head*32+d]

__device__ __forceinline__ float t32(float x) { return wmma::__float_to_tf32(x); }

// ---------------------------------------------------------------------------
// cp.async helpers
// ---------------------------------------------------------------------------
__device__ __forceinline__ void cp_async16(void* smem, const void* gmem) {
    unsigned s = (unsigned)__cvta_generic_to_shared(smem);
    asm volatile("cp.async.cg.shared.global [%0], [%1], 16;\n" :: "r"(s), "l"(gmem));
}
__device__ __forceinline__ void cp_commit() { asm volatile("cp.async.commit_group;\n"); }
__device__ __forceinline__ void cp_wait1()  { asm volatile("cp.async.wait_group 1;\n"); }
__device__ __forceinline__ void cp_wait0()  { asm volatile("cp.async.wait_group 0;\n"); }

// ---------------------------------------------------------------------------
// TF32 GEMM: C[M,N] = A[M,256]@B[256,N] (+bias). BM=BN=128, BK=32, 2-stage.
// 256 thr = 8 warps (2x4); warp tile 64x32. Dynamic smem 70656B, 2 CTA/SM.
// ---------------------------------------------------------------------------
__global__ __launch_bounds__(256, 2) void gemm_wmma(
    const float* __restrict__ A, const float* __restrict__ B,
    const float* __restrict__ bias, float* __restrict__ C, int N)
{
    extern __shared__ float sm[];
    float* As = sm;          // [2][128][36]  stage stride 4608
    float* Bs = sm + 9216;   // [2][32][132]  stage stride 4224

    const int tid  = threadIdx.x;
    const int warp = tid >> 5;
    const int lane = tid & 31;
    const int wm = warp >> 2, wn = warp & 3;
    const int bn = blockIdx.x * 128;   // fast dim = cols -> A L2 reuse
    const int bm = blockIdx.y * 128;

    wmma::fragment<wmma::accumulator, 16, 16, 8, float> acc[4][2];
#pragma unroll
    for (int i = 0; i < 4; i++)
#pragma unroll
        for (int j = 0; j < 2; j++) wmma::fill_fragment(acc[i][j], 0.f);

    auto load_tile = [&](int s, int k0) {
#pragma unroll
        for (int t = 0; t < 4; t++) {
            int idx = tid + t * 256;                 // 0..1023
            int ar = idx >> 3, ac = (idx & 7) * 4;   // A: 128x32
            cp_async16(&As[s * 4608 + ar * 36 + ac],
                       A + (size_t)(bm + ar) * 256 + k0 + ac);
            int br = idx >> 5, bc = (idx & 31) * 4;  // B: 32x128
            cp_async16(&Bs[s * 4224 + br * 132 + bc],
                       B + (size_t)(k0 + br) * N + bn + bc);
        }
        cp_commit();
    };

    load_tile(0, 0);
    const int NK = 8;  // 256/32
    for (int kt = 0; kt < NK; kt++) {
        const int cur = kt & 1;
        if (kt + 1 < NK) { load_tile(cur ^ 1, (kt + 1) * 32); cp_wait1(); }
        else             { cp_wait0(); }
        __syncthreads();
#pragma unroll
        for (int kk = 0; kk < 32; kk += 8) {
            wmma::fragment<wmma::matrix_a, 16, 16, 8, wmma::precision::tf32,
                           wmma::row_major> af[4];
            wmma::fragment<wmma::matrix_b, 16, 16, 8, wmma::precision::tf32,
                           wmma::row_major> bf[2];
#pragma unroll
            for (int i = 0; i < 4; i++) {
                wmma::load_matrix_sync(af[i], &As[cur * 4608 + (wm * 64 + i * 16) * 36 + kk], 36);
#pragma unroll
                for (int e = 0; e < af[i].num_elements; e++) af[i].x[e] = t32(af[i].x[e]);
            }
#pragma unroll
            for (int j = 0; j < 2; j++) {
                wmma::load_matrix_sync(bf[j], &Bs[cur * 4224 + kk * 132 + wn * 32 + j * 16], 132);
#pragma unroll
                for (int e = 0; e < bf[j].num_elements; e++) bf[j].x[e] = t32(bf[j].x[e]);
            }
#pragma unroll
            for (int i = 0; i < 4; i++)
#pragma unroll
                for (int j = 0; j < 2; j++)
                    wmma::mma_sync(acc[i][j], af[i], bf[j], acc[i][j]);
        }
        __syncthreads();
    }

    // Epilogue via private smem strip
    float* wb = sm + warp * 320;   // 16 x 20
    const int r = lane >> 1, c0 = (lane & 1) * 8;
#pragma unroll
    for (int i = 0; i < 4; i++) {
#pragma unroll
        for (int j = 0; j < 2; j++) {
            wmma::store_matrix_sync(wb, acc[i][j], 20, wmma::mem_row_major);
            __syncwarp();
            float4 v0 = *(float4*)&wb[r * 20 + c0];
            float4 v1 = *(float4*)&wb[r * 20 + c0 + 4];
            int grow = bm + wm * 64 + i * 16 + r;
            int gcol = bn + wn * 32 + j * 16 + c0;
            if (bias) {
                v0.x += bias[gcol + 0]; v0.y += bias[gcol + 1];
                v0.z += bias[gcol + 2]; v0.w += bias[gcol + 3];
                v1.x += bias[gcol + 4]; v1.y += bias[gcol + 5];
                v1.z += bias[gcol + 6]; v1.w += bias[gcol + 7];
            }
            *(float4*)&C[(size_t)grow * N + gcol]     = v0;
            *(float4*)&C[(size_t)grow * N + gcol + 4] = v1;
            __syncwarp();
        }
    }
}

// ---------------------------------------------------------------------------
// Local window attention via tensor cores. CTA = 1 window x 2 heads.
// Per head (floats): Q[64][36]=2304, Kt[32][68]=2176, V[64][36]=2304,
//                    S[64][68]=4352, invl[64]. Head stride 11200.
// 256 thr = 8 warps, 4 per head. Dyn smem 89600B.
// ---------------------------------------------------------------------------
__global__ __launch_bounds__(256, 2) void attn_local_tc(
    const float* __restrict__ qkv, float* __restrict__ att)
{
    extern __shared__ float sm[];
    const int wid = blockIdx.x;
    const int b = wid >> 8, wy = (wid >> 4) & 15, wx = wid & 15;
    const int tid = threadIdx.x;
    const int warp = tid >> 5;
    const int hh = warp >> 2, wl = warp & 3;
    const float scale = 0.17677669529663687f;

    // Stage Q(scaled), Kt (transposed), V — tf32-rounded
#pragma unroll
    for (int i = 0; i < 4; i++) {
        int idx = tid + i * 256;           // 0..1023
        int h2 = idx >> 9;
        int r  = (idx >> 3) & 63;
        int c  = (idx & 7) * 4;
        int hg = (int)blockIdx.y * 2 + h2;
        size_t token = ((size_t)(b * 128 + wy * 8 + (r >> 3))) * 128 + wx * 8 + (r & 7);
        const float* base = qkv + token * 768 + hg * 32 + c;
        float4 q4 = *(const float4*)base;
        float4 k4 = *(const float4*)(base + 256);
        float4 v4 = *(const float4*)(base + 512);
        float* Q = sm + h2 * 11200;
        float* Kt = Q + 2304;
        float* V = Q + 4480;
        Q[r * 36 + c + 0] = t32(q4.x * scale);
        Q[r * 36 + c + 1] = t32(q4.y * scale);
        Q[r * 36 + c + 2] = t32(q4.z * scale);
        Q[r * 36 + c + 3] = t32(q4.w * scale);
        Kt[(c + 0) * 68 + r] = t32(k4.x);
        Kt[(c + 1) * 68 + r] = t32(k4.y);
        Kt[(c + 2) * 68 + r] = t32(k4.z);
        Kt[(c + 3) * 68 + r] = t32(k4.w);
        V[r * 36 + c + 0] = t32(v4.x);
        V[r * 36 + c + 1] = t32(v4.y);
        V[r * 36 + c + 2] = t32(v4.z);
        V[r * 36 + c + 3] = t32(v4.w);
    }
    __syncthreads();

    float* Qh  = sm + hh * 11200;
    float* Kth = Qh + 2304;
    float* Vh  = Qh + 4480;
    float* Sh  = Qh + 6784;
    float* il  = Qh + 11136;

    // S = Q @ K^T  (64x64, k=32)
    {
        wmma::fragment<wmma::accumulator, 16, 16, 8, float> accS[4];
#pragma unroll
        for (int j = 0; j < 4; j++) wmma::fill_fragment(accS[j], 0.f);
#pragma unroll
        for (int kk = 0; kk < 32; kk += 8) {
            wmma::fragment<wmma::matrix_a, 16, 16, 8, wmma::precision::tf32,
                           wmma::row_major> af;
            wmma::load_matrix_sync(af, &Qh[(wl * 16) * 36 + kk], 36);
#pragma unroll
            for (int j = 0; j < 4; j++) {
                wmma::fragment<wmma::matrix_b, 16, 16, 8, wmma::precision::tf32,
                               wmma::row_major> bf;
                wmma::load_matrix_sync(bf, &Kth[kk * 68 + j * 16], 68);
                wmma::mma_sync(accS[j], af, bf, accS[j]);
            }
        }
#pragma unroll
        for (int j = 0; j < 4; j++)
            wmma::store_matrix_sync(&Sh[(wl * 16) * 68 + j * 16], accS[j], 68,
                                    wmma::mem_row_major);
    }
    __syncthreads();

    // Softmax: 128 thr/head, 2 thr/row (halves of 32), shfl combine
    {
        int h2 = tid >> 7, local = tid & 127;
        int row = local >> 1, half = local & 1;
        float* S = sm + h2 * 11200 + 6784 + row * 68 + half * 32;
        float m = -3.0e38f;
#pragma unroll
        for (int e = 0; e < 32; e++) m = fmaxf(m, S[e]);
        m = fmaxf(m, __shfl_xor_sync(0xffffffffu, m, 1));
        float sum = 0.f;
#pragma unroll
        for (int e = 0; e < 32; e++) {
            float p = __expf(S[e] - m);
            S[e] = t32(p);
            sum += p;
        }
        sum += __shfl_xor_sync(0xffffffffu, sum, 1);
        if (half == 0) (sm + h2 * 11200 + 11136)[row] = 1.f / sum;
    }
    __syncthreads();

    // O = P @ V  (64x32, k=64) -> store into Q strip
    {
        wmma::fragment<wmma::accumulator, 16, 16, 8, float> accO[2];
#pragma unroll
        for (int j = 0; j < 2; j++) wmma::fill_fragment(accO[j], 0.f);
#pragma unroll
        for (int kk = 0; kk < 64; kk += 8) {
            wmma::fragment<wmma::matrix_a, 16, 16, 8, wmma::precision::tf32,
                           wmma::row_major> af;
            wmma::load_matrix_sync(af, &Sh[(wl * 16) * 68 + kk], 68);
#pragma unroll
            for (int j = 0; j < 2; j++) {
                wmma::fragment<wmma::matrix_b, 16, 16, 8, wmma::precision::tf32,
                               wmma::row_major> bf;
                wmma::load_matrix_sync(bf, &Vh[kk * 36 + j * 16], 36);
                wmma::mma_sync(accO[j], af, bf, accO[j]);
            }
        }
#pragma unroll
        for (int j = 0; j < 2; j++)
            wmma::store_matrix_sync(&Qh[(wl * 16) * 36 + j * 16], accO[j], 36,
                                    wmma::mem_row_major);
    }
    __syncthreads();

    // Write out normalized
#pragma unroll
    for (int i = 0; i < 4; i++) {
        int idx = tid + i * 256;
        int h2 = idx >> 9;
        int r  = (idx >> 3) & 63;
        int c  = (idx & 7) * 4;
        int hg = (int)blockIdx.y * 2 + h2;
        float* Q = sm + h2 * 11200;
        float inv = (sm + h2 * 11200 + 11136)[r];
        float4 o = make_float4(Q[r * 36 + c] * inv, Q[r * 36 + c + 1] * inv,
                               Q[r * 36 + c + 2] * inv, Q[r * 36 + c + 3] * inv);
        size_t token = ((size_t)(b * 128 + wy * 8 + (r >> 3))) * 128 + wx * 8 + (r & 7);
        *(float4*)&att[token * 256 + hg * 32 + c] = o;
    }
}

// ---------------------------------------------------------------------------
// Grid (dilated) attention via tensor cores. CTA = (cell, head, 64-query tile).
// smem (floats): Q[64][36]@0, Kt[32][260]@2304, V[256][36]@10624,
//                S[64][260]@19840, invl[64]@36480. Total 36544 fl = 146176B.
// 256 thr = 8 warps: warp (wl=row-tile, wc=col-half).
// ---------------------------------------------------------------------------
__global__ __launch_bounds__(256, 1) void attn_grid_tc(
    const float* __restrict__ qkv, float* __restrict__ att)
{
    extern __shared__ float sm[];
    const int cid = blockIdx.x;
    const int b = cid >> 6, s1 = (cid >> 3) & 7, s2 = cid & 7;
    const int hq = blockIdx.y;
    const int h = 4 + (hq >> 2), qt = hq & 3;
    const int tid = threadIdx.x;
    const int warp = tid >> 5;
    const int wl = warp & 3, wc = warp >> 2;
    const float scale = 0.17677669529663687f;

    float* Q  = sm;
    float* Kt = sm + 2304;
    float* V  = sm + 10624;
    float* S  = sm + 19840;
    float* il = sm + 36480;

    // Stage Q (64 rows of this qtile)
#pragma unroll
    for (int i = 0; i < 2; i++) {
        int idx = tid + i * 256;           // 0..511
        int r = idx >> 3, c = (idx & 7) * 4;
        int qq = qt * 64 + r;
        size_t token = ((size_t)(b * 128 + (qq >> 4) * 8 + s1)) * 128 + (qq & 15) * 8 + s2;
        float4 q4 = *(const float4*)(qkv + token * 768 + h * 32 + c);
        Q[r * 36 + c + 0] = t32(q4.x * scale);
        Q[r * 36 + c + 1] = t32(q4.y * scale);
        Q[r * 36 + c + 2] = t32(q4.z * scale);
        Q[r * 36 + c + 3] = t32(q4.w * scale);
    }
    // Stage K (transposed) and V (256 keys)
#pragma unroll
    for (int i = 0; i < 8; i++) {
        int idx = tid + i * 256;           // 0..2047
        int rk = idx >> 3, c = (idx & 7) * 4;
        size_t ktok = ((size_t)(b * 128 + (rk >> 4) * 8 + s1)) * 128 + (rk & 15) * 8 + s2;
        const float* base = qkv + ktok * 768 + h * 32 + c;
        float4 k4 = *(const float4*)(base + 256);
        float4 v4 = *(const float4*)(base + 512);
        Kt[(c + 0) * 260 + rk] = t32(k4.x);
        Kt[(c + 1) * 260 + rk] = t32(k4.y);
        Kt[(c + 2) * 260 + rk] = t32(k4.z);
        Kt[(c + 3) * 260 + rk] = t32(k4.w);
        V[rk * 36 + c + 0] = t32(v4.x);
        V[rk * 36 + c + 1] = t32(v4.y);
        V[rk * 36 + c + 2] = t32(v4.z);
        V[rk * 36 + c + 3] = t32(v4.w);
    }
    __syncthreads();

    // S = Q @ K^T  (64 x 256, k=32); warp covers (row-tile wl, col tiles wc*8..+7)
    {
        wmma::fragment<wmma::matrix_a, 16, 16, 8, wmma::precision::tf32,
                       wmma::row_major> af[4];
#pragma unroll
        for (int ki = 0; ki < 4; ki++)
            wmma::load_matrix_sync(af[ki], &Q[(wl * 16) * 36 + ki * 8], 36);
        for (int j = wc * 8; j < wc * 8 + 8; j++) {
            wmma::fragment<wmma::accumulator, 16, 16, 8, float> acc;
            wmma::fill_fragment(acc, 0.f);
#pragma unroll
            for (int ki = 0; ki < 4; ki++) {
                wmma::fragment<wmma::matrix_b, 16, 16, 8, wmma::precision::tf32,
                               wmma::row_major> bf;
                wmma::load_matrix_sync(bf, &Kt[(ki * 8) * 260 + j * 16], 260);
                wmma::mma_sync(acc, af[ki], bf, acc);
            }
            wmma::store_matrix_sync(&S[(wl * 16) * 260 + j * 16], acc, 260,
                                    wmma::mem_row_major);
        }
    }
    __syncthreads();

    // Softmax: 4 thr/row, 64 elems each, shfl combine within lane quads
    {
        int row = tid >> 2, quarter = tid & 3;
        float* Sp = S + row * 260 + quarter * 64;
        float m = -3.0e38f;
#pragma unroll
        for (int e = 0; e < 64; e++) m = fmaxf(m, Sp[e]);
        m = fmaxf(m, __shfl_xor_sync(0xffffffffu, m, 1));
        m = fmaxf(m, __shfl_xor_sync(0xffffffffu, m, 2));
        float sum = 0.f;
#pragma unroll
        for (int e = 0; e < 64; e++) {
            float p = __expf(Sp[e] - m);
            Sp[e] = t32(p);
            sum += p;
        }
        sum += __shfl_xor_sync(0xffffffffu, sum, 1);
        sum += __shfl_xor_sync(0xffffffffu, sum, 2);
        if (quarter == 0) il[row] = 1.f / sum;
    }
    __syncthreads();

    // O = P @ V (64x32, k=256); warp does (row-tile wl, col-tile wc)
    {
        wmma::fragment<wmma::accumulator, 16, 16, 8, float> acc;
        wmma::fill_fragment(acc, 0.f);
#pragma unroll 4
        for (int ks = 0; ks < 32; ks++) {
            int kk = ks * 8;
            wmma::fragment<wmma::matrix_a, 16, 16, 8, wmma::precision::tf32,
                           wmma::row_major> af;
            wmma::fragment<wmma::matrix_b, 16, 16, 8, wmma::precision::tf32,
                           wmma::row_major> bf;
            wmma::load_matrix_sync(af, &S[(wl * 16) * 260 + kk], 260);
            wmma::load_matrix_sync(bf, &V[kk * 36 + wc * 16], 36);
            wmma::mma_sync(acc, af, bf, acc);
        }
        wmma::store_matrix_sync(&Q[(wl * 16) * 36 + wc * 16], acc, 36,
                                wmma::mem_row_major);
    }
    __syncthreads();

    // Write out normalized
#pragma unroll
    for (int i = 0; i < 2; i++) {
        int idx = tid + i * 256;
        int r = idx >> 3, c = (idx & 7) * 4;
        float inv = il[r];
        float4 o = make_float4(Q[r * 36 + c] * inv, Q[r * 36 + c + 1] * inv,
                               Q[r * 36 + c + 2] * inv, Q[r * 36 + c + 3] * inv);
        int qq = qt * 64 + r;
        size_t token = ((size_t)(b * 128 + (qq >> 4) * 8 + s1)) * 128 + (qq & 15) * 8 + s2;
        *(float4*)&att[token * 256 + h * 32 + c] = o;
    }
}

// ---------------------------------------------------------------------------
extern "C" void kernel_launch(void* const* d_in, const int* in_sizes, int n_in,
                              void* d_out, int out_size)
{
    (void)in_sizes; (void)n_in; (void)out_size;
    const float* x     = (const float*)d_in[0];
    const float* Wqkv  = (const float*)d_in[1];
    const float* Wproj = (const float*)d_in[2];
    const float* bproj = (const float*)d_in[3];
    float* out = (float*)d_out;

    float* qkv = nullptr;
    float* att = nullptr;
    cudaGetSymbolAddress((void**)&qkv, g_qkv);
    cudaGetSymbolAddress((void**)&att, g_att);

    cudaFuncSetAttribute(gemm_wmma, cudaFuncAttributeMaxDynamicSharedMemorySize, 70656);
    cudaFuncSetAttribute(attn_local_tc, cudaFuncAttributeMaxDynamicSharedMemorySize, 89600);
    cudaFuncSetAttribute(attn_grid_tc, cudaFuncAttributeMaxDynamicSharedMemorySize, 146176);

    // 1) QKV = x @ W_qkv
    gemm_wmma<<<dim3(6, 1024), 256, 70656>>>(x, Wqkv, nullptr, qkv, 768);
    // 2) local window attention (heads 0..3)
    attn_local_tc<<<dim3(2048, 2), 256, 89600>>>(qkv, att);
    // 3) dilated grid attention (heads 4..7)
    attn_grid_tc<<<dim3(512, 16), 256, 146176>>>(qkv, att);
    // 4) out = att @ W_proj + b_proj
    gemm_wmma<<<dim3(2, 1024), 256, 70656>>>(att, Wproj, bproj, out, 256);
}